// round 9
// baseline (speedup 1.0000x reference)
#include <cuda_runtime.h>
#include <cuda_fp16.h>
#include <math.h>
#include <stdint.h>

#define T_TOK 32768
#define C_DIM 768
#define E_NUM 4
#define HD_DIM 192
#define KB 64                           // 64 halfs per k-iter (128B rows)
#define STG_B 32768                     // bytes per stage: A 16KB + B 16KB
#define TBL_OFF (3 * STG_B)             // ptr tables after stages
#define SMEM_TOT (3 * STG_B + 2048 + 512 + 128)

__device__ float  g_combine[T_TOK * E_NUM];
__device__ int    g_pair[T_TOK];
__device__ int    g_cnt[8];
__device__ int    g_bucket[6 * T_TOK];
__device__ __half g_xh[(size_t)T_TOK * C_DIM];        // 50 MB fp16(x)
__device__ __half g_hmid[(size_t)T_TOK * 384];        // 25 MB fp16(gelu*cw), pair-packed
__device__ __half g_w1h[E_NUM * HD_DIM * C_DIM];      // 1.2 MB
__device__ __half g_w2h[E_NUM * C_DIM * HD_DIM];      // 1.2 MB

__constant__ int c_pairs[6][2] = {{0,1},{0,2},{0,3},{1,2},{1,3},{2,3}};

// ---------------- helpers ----------------
__device__ __forceinline__ uint32_t smem_u32(const void* p) {
    uint32_t a;
    asm("{ .reg .u64 t; cvta.to.shared.u64 t, %1; cvt.u32.u64 %0, t; }" : "=r"(a) : "l"(p));
    return a;
}
#define CPA(s, g)  asm volatile("cp.async.cg.shared.global [%0], [%1], 16;" :: "r"(s), "l"(g))
#define CPC()      asm volatile("cp.async.commit_group;" ::: "memory")
#define CPW(n)     asm volatile("cp.async.wait_group %0;" :: "n"(n) : "memory")

#define LDSM4(r0, r1, r2, r3, addr)                                                     \
    asm volatile("ldmatrix.sync.aligned.m8n8.x4.shared.b16 {%0,%1,%2,%3}, [%4];"        \
                 : "=r"(r0), "=r"(r1), "=r"(r2), "=r"(r3) : "r"(addr))

#define MMA16(c, a, b)                                                                  \
    asm volatile("mma.sync.aligned.m16n8k16.row.col.f32.f16.f16.f32 "                   \
                 "{%0,%1,%2,%3},{%4,%5,%6,%7},{%8,%9},{%0,%1,%2,%3};"                   \
                 : "+f"((c)[0]), "+f"((c)[1]), "+f"((c)[2]), "+f"((c)[3])               \
                 : "r"((a)[0]), "r"((a)[1]), "r"((a)[2]), "r"((a)[3]),                  \
                   "r"((b)[0]), "r"((b)[1]))

// 128-row x 64-half tile via precomputed row pointers: LDS.64 + add + swizzle
__device__ __forceinline__ void ld_tile_p(uint32_t sbase, const uint64_t* __restrict__ rp,
                                          uint32_t koff, int tid) {
    #pragma unroll
    for (int c = tid; c < 1024; c += 256) {
        int row = c >> 3, ch = c & 7;
        const char* gp = (const char*)(rp[row] + koff) + ch * 16;
        uint32_t off = (uint32_t)(row * 128 + ((ch ^ (row & 7)) << 4));
        CPA(sbase + off, gp);
    }
}

// ---------------------------------------------------------------------------
__global__ __launch_bounds__(256) void round_w_kernel(const float* __restrict__ w1,
                                                      const float* __restrict__ w2)
{
    const int N1 = E_NUM * HD_DIM * C_DIM;
    int i = blockIdx.x * 256 + threadIdx.x;
    if (i < N1) {
        g_w1h[i] = __float2half_rn(w1[i]);
        g_w2h[i] = __float2half_rn(w2[i]);
    }
}

// ---------------------------------------------------------------------------
// Router: warp per token -> combine + pair id; writes fp16 x row.
// ---------------------------------------------------------------------------
__global__ __launch_bounds__(256) void router_kernel(
    const float* __restrict__ x, const float* __restrict__ rw, const float* __restrict__ rb)
{
    if (blockIdx.x == 0 && threadIdx.x < 8) g_cnt[threadIdx.x] = 0;
    int warp = threadIdx.x >> 5, lane = threadIdx.x & 31;
    int t = blockIdx.x * 8 + warp;
    const float* xr = x + (size_t)t * C_DIM;
    __half* xo = g_xh + (size_t)t * C_DIM;
    float a0 = 0.f, a1 = 0.f, a2 = 0.f, a3 = 0.f;
    for (int c = lane * 4; c < C_DIM; c += 128) {
        float4 xv = *(const float4*)(xr + c);
        float4 w0 = *(const float4*)(rw + 0 * C_DIM + c);
        float4 w1 = *(const float4*)(rw + 1 * C_DIM + c);
        float4 w2 = *(const float4*)(rw + 2 * C_DIM + c);
        float4 w3 = *(const float4*)(rw + 3 * C_DIM + c);
        a0 += xv.x*w0.x + xv.y*w0.y + xv.z*w0.z + xv.w*w0.w;
        a1 += xv.x*w1.x + xv.y*w1.y + xv.z*w1.z + xv.w*w1.w;
        a2 += xv.x*w2.x + xv.y*w2.y + xv.z*w2.z + xv.w*w2.w;
        a3 += xv.x*w3.x + xv.y*w3.y + xv.z*w3.z + xv.w*w3.w;
        __half2 h0 = __floats2half2_rn(xv.x, xv.y);
        __half2 h1 = __floats2half2_rn(xv.z, xv.w);
        *(uint2*)(xo + c) = make_uint2(*(uint32_t*)&h0, *(uint32_t*)&h1);
    }
    #pragma unroll
    for (int o = 16; o > 0; o >>= 1) {
        a0 += __shfl_xor_sync(0xffffffffu, a0, o);
        a1 += __shfl_xor_sync(0xffffffffu, a1, o);
        a2 += __shfl_xor_sync(0xffffffffu, a2, o);
        a3 += __shfl_xor_sync(0xffffffffu, a3, o);
    }
    if (lane == 0) {
        float l[4] = { a0 + rb[0], a1 + rb[1], a2 + rb[2], a3 + rb[3] };
        float mx = fmaxf(fmaxf(l[0], l[1]), fmaxf(l[2], l[3]));
        float p[4]; float Z = 0.f;
        #pragma unroll
        for (int e = 0; e < 4; e++) { p[e] = expf(l[e] - mx); Z += p[e]; }
        #pragma unroll
        for (int e = 0; e < 4; e++) p[e] /= Z;
        int i0 = 0;
        #pragma unroll
        for (int e = 1; e < 4; e++) if (p[e] > p[i0]) i0 = e;
        int i1 = (i0 == 0) ? 1 : 0;
        #pragma unroll
        for (int e = 0; e < 4; e++) if (e != i0 && p[e] > p[i1]) i1 = e;
        float s = p[i0] + p[i1] + 1e-8f;
        float ov[4] = {0.f, 0.f, 0.f, 0.f};
        ov[i0] = p[i0] / s; ov[i1] = p[i1] / s;
        ((float4*)g_combine)[t] = make_float4(ov[0], ov[1], ov[2], ov[3]);
        int lo = min(i0, i1), hi = max(i0, i1);
        g_pair[t] = (lo == 0) ? hi - 1 : ((lo == 1) ? hi + 1 : 5);
    }
}

// ---------------------------------------------------------------------------
__global__ __launch_bounds__(256) void bucketize_kernel()
{
    int t = blockIdx.x * 256 + threadIdx.x;
    int pid = g_pair[t];
    unsigned mask = __match_any_sync(0xffffffffu, pid);
    int leader = __ffs(mask) - 1;
    int rank = __popc(mask & ((1u << (threadIdx.x & 31)) - 1));
    int base = 0;
    if ((threadIdx.x & 31) == leader) base = atomicAdd(&g_cnt[pid], __popc(mask));
    base = __shfl_sync(0xffffffffu, base, leader);
    g_bucket[pid * T_TOK + base + rank] = t;
}

// ---------------------------------------------------------------------------
// Grouped fp16 mma GEMM over pair buckets. 128x128 tile, KB=64, ldmatrix,
// k-invariant row pointers precomputed in smem.
// ---------------------------------------------------------------------------
template <int MODE>
__global__ __launch_bounds__(256, 2)
void moe_mma(const float* __restrict__ bias, float* __restrict__ outp)
{
    constexpr int NKI = (MODE == 1) ? (C_DIM / KB) : (384 / KB);   // 12 / 6
    extern __shared__ __align__(128) char smc[];
    const uint32_t sb = smem_u32(smc);
    uint64_t* rpA = (uint64_t*)(smc + TBL_OFF);            // 128 x 8B
    uint64_t* rpB = rpA + 128;                             // 128 x 8B
    int* stok = (int*)(rpB + 128);                         // 128 x 4B

    const int b = blockIdx.z;
    const int cnt = __ldg(&g_cnt[b]);
    const int m0 = blockIdx.y * 128;
    if (m0 >= cnt) return;
    const int n0 = blockIdx.x * 128;
    const int e0 = c_pairs[b][0], e1 = c_pairs[b][1];

    const int tid = threadIdx.x, lane = tid & 31, w = tid >> 5;
    const int wm = w & 1, wn = w >> 1;
    const int lq = lane >> 2, lr = lane & 3;

    if (tid < 128) {
        int p = m0 + tid;
        int t = g_bucket[b * T_TOK + (p < cnt ? p : m0)];
        stok[tid] = t;
        rpA[tid] = (MODE == 1)
            ? (uint64_t)(const char*)(g_xh + (size_t)t * C_DIM)
            : (uint64_t)(const char*)(g_hmid + (size_t)t * 384);
    } else {
        int row = tid - 128;
        if (MODE == 1) {
            int n = n0 + row;
            int e = (n < HD_DIM) ? e0 : e1;
            int h = (n < HD_DIM) ? n : n - HD_DIM;
            rpB[row] = (uint64_t)(const char*)(g_w1h + ((size_t)e * HD_DIM + h) * C_DIM);
        } else {
            rpB[row] = (uint64_t)(const char*)(g_w2h + (size_t)(n0 + row) * HD_DIM);
        }
    }
    __syncthreads();

    // per-iter byte offsets added to row pointers
    auto koffB = [&](int i) -> uint32_t {
        if (MODE == 1) return (uint32_t)(i * 128);
        int e = i / 3;                             // KB=64, HD=192 -> 3 iters per expert
        int h0 = (i - e * 3) * KB;
        return (uint32_t)(((e == 0) ? e0 : e1) * C_DIM * HD_DIM + h0) * 2u;
    };

    // ldmatrix per-lane address components (rows of 128B, swizzle chunk^=(row&7))
    const int ms = lane >> 3, rl = lane & 7;
    const int a_ms2 = ms >> 1;
    const int b_ms1 = ms & 1;
    uint32_t a_rowoff[4], b_rowoff[2];
    #pragma unroll
    for (int mi = 0; mi < 4; mi++)
        a_rowoff[mi] = (uint32_t)((wm * 64 + mi * 16 + (ms & 1) * 8 + rl) * 128);
    #pragma unroll
    for (int p = 0; p < 2; p++)
        b_rowoff[p] = (uint32_t)((wn * 32 + p * 16 + (ms >> 1) * 8 + rl) * 128);

    float acc[4][4][4] = {};

    #pragma unroll
    for (int p = 0; p < 2; p++) {
        ld_tile_p(sb + p * STG_B, rpA, (uint32_t)(p * 128), tid);
        ld_tile_p(sb + p * STG_B + 16384, rpB, koffB(p), tid);
        CPC();
    }

    for (int i = 0; i < NKI; i++) {
        if (i < NKI - 1) { CPW(1); } else { CPW(0); }
        __syncthreads();
        if (i + 2 < NKI) {
            const int s2 = (i + 2) % 3;
            ld_tile_p(sb + s2 * STG_B, rpA, (uint32_t)((i + 2) * 128), tid);
            ld_tile_p(sb + s2 * STG_B + 16384, rpB, koffB(i + 2), tid);
            CPC();
        }
        const uint32_t smA = sb + (i % 3) * STG_B;
        const uint32_t smB = smA + 16384;

        #pragma unroll
        for (int kk = 0; kk < 4; kk++) {
            uint32_t a[4][4], bb[4][2];
            const uint32_t koA = (uint32_t)(((2 * kk + a_ms2) ^ rl) << 4);
            const uint32_t koB = (uint32_t)(((2 * kk + b_ms1) ^ rl) << 4);
            #pragma unroll
            for (int mi = 0; mi < 4; mi++)
                LDSM4(a[mi][0], a[mi][1], a[mi][2], a[mi][3], smA + a_rowoff[mi] + koA);
            #pragma unroll
            for (int p = 0; p < 2; p++)
                LDSM4(bb[2*p][0], bb[2*p][1], bb[2*p+1][0], bb[2*p+1][1],
                      smB + b_rowoff[p] + koB);
            #pragma unroll
            for (int mi = 0; mi < 4; mi++)
                #pragma unroll
                for (int nj = 0; nj < 4; nj++)
                    MMA16(acc[mi][nj], a[mi], bb[nj]);
        }
        __syncthreads();
    }

    // ---------------- epilogue ----------------
    #pragma unroll
    for (int mi = 0; mi < 4; mi++) {
        #pragma unroll
        for (int half = 0; half < 2; half++) {
            const int rloc = wm * 64 + mi * 16 + lq + half * 8;
            if (m0 + rloc >= cnt) continue;
            const int t = stok[rloc];
            if (MODE == 1) {
                __half* orow = g_hmid + (size_t)t * 384;
                #pragma unroll
                for (int nj = 0; nj < 4; nj++) {
                    const int n = n0 + wn * 32 + nj * 8 + lr * 2;
                    const int e = (n < HD_DIM) ? e0 : e1;
                    const int h = (n < HD_DIM) ? n : n - HD_DIM;
                    const float cw = g_combine[t * 4 + e];
                    float vv[2];
                    #pragma unroll
                    for (int u = 0; u < 2; u++) {
                        float d = acc[mi][nj][half * 2 + u] + __ldg(&bias[e * HD_DIM + h + u]);
                        float g = 0.5f * d * (1.0f + erff(d * 0.70710678118654752f));
                        vv[u] = g * cw;
                    }
                    __half2 hv = __floats2half2_rn(vv[0], vv[1]);
                    *(__half2*)(orow + n) = hv;
                }
            } else {
                const float4 cw = ((const float4*)g_combine)[t];
                float* orow = outp + (size_t)t * C_DIM;
                #pragma unroll
                for (int nj = 0; nj < 4; nj++) {
                    const int n = n0 + wn * 32 + nj * 8 + lr * 2;
                    float2 v;
                    #pragma unroll
                    for (int u = 0; u < 2; u++) {
                        const int c = n + u;
                        float bv = cw.x * __ldg(&bias[0 * C_DIM + c])
                                 + cw.y * __ldg(&bias[1 * C_DIM + c])
                                 + cw.z * __ldg(&bias[2 * C_DIM + c])
                                 + cw.w * __ldg(&bias[3 * C_DIM + c]);
                        ((float*)&v)[u] = acc[mi][nj][half * 2 + u] + bv;
                    }
                    *(float2*)(orow + n) = v;
                }
            }
        }
    }
}

// ---------------------------------------------------------------------------
extern "C" void kernel_launch(void* const* d_in, const int* in_sizes, int n_in,
                              void* d_out, int out_size)
{
    const float* x  = (const float*)d_in[0];
    const float* rw = (const float*)d_in[1];
    const float* rb = (const float*)d_in[2];
    const float* w1 = (const float*)d_in[3];
    const float* b1 = (const float*)d_in[4];
    const float* w2 = (const float*)d_in[5];
    const float* b2 = (const float*)d_in[6];
    float* out = (float*)d_out;

    cudaFuncSetAttribute(moe_mma<1>, cudaFuncAttributeMaxDynamicSharedMemorySize, SMEM_TOT);
    cudaFuncSetAttribute(moe_mma<2>, cudaFuncAttributeMaxDynamicSharedMemorySize, SMEM_TOT);

    round_w_kernel<<<(E_NUM * HD_DIM * C_DIM + 255) / 256, 256>>>(w1, w2);
    router_kernel<<<T_TOK / 8, 256>>>(x, rw, rb);
    bucketize_kernel<<<T_TOK / 256, 256>>>();
    moe_mma<1><<<dim3(3, T_TOK / 128, 6), 256, SMEM_TOT>>>(b1, nullptr);
    moe_mma<2><<<dim3(6, T_TOK / 128, 6), 256, SMEM_TOT>>>(b2, out);
}

// round 10
// speedup vs baseline: 1.0494x; 1.0494x over previous
#include <cuda_runtime.h>
#include <cuda_fp16.h>
#include <math.h>
#include <stdint.h>

#define T_TOK 32768
#define C_DIM 768
#define E_NUM 4
#define HD_DIM 192
#define KB 64                           // 64 halfs per k-iter (128B rows)
#define STG_B 32768                     // bytes per stage: A 16KB + B 16KB
#define TBL_OFF (3 * STG_B)
#define SMEM_TOT (3 * STG_B + 2048 + 512 + 128)

__device__ float  g_combine[T_TOK * E_NUM];
__device__ int    g_pair[T_TOK];
__device__ int    g_cnt[8];
__device__ int    g_item;
__device__ int    g_done[8];
__device__ int    g_bucket[6 * T_TOK];
__device__ __half g_xh[(size_t)T_TOK * C_DIM];
__device__ __half g_hmid[(size_t)T_TOK * 384];
__device__ __half g_w1h[E_NUM * HD_DIM * C_DIM];
__device__ __half g_w2h[E_NUM * C_DIM * HD_DIM];

__constant__ int c_pairs[6][2] = {{0,1},{0,2},{0,3},{1,2},{1,3},{2,3}};

// ---------------- helpers ----------------
__device__ __forceinline__ uint32_t smem_u32(const void* p) {
    uint32_t a;
    asm("{ .reg .u64 t; cvta.to.shared.u64 t, %1; cvt.u32.u64 %0, t; }" : "=r"(a) : "l"(p));
    return a;
}
#define CPA(s, g)  asm volatile("cp.async.cg.shared.global [%0], [%1], 16;" :: "r"(s), "l"(g))
#define CPC()      asm volatile("cp.async.commit_group;" ::: "memory")
#define CPW(n)     asm volatile("cp.async.wait_group %0;" :: "n"(n) : "memory")

#define LDSM4(r0, r1, r2, r3, addr)                                                     \
    asm volatile("ldmatrix.sync.aligned.m8n8.x4.shared.b16 {%0,%1,%2,%3}, [%4];"        \
                 : "=r"(r0), "=r"(r1), "=r"(r2), "=r"(r3) : "r"(addr))

#define MMA16(c, a, b)                                                                  \
    asm volatile("mma.sync.aligned.m16n8k16.row.col.f32.f16.f16.f32 "                   \
                 "{%0,%1,%2,%3},{%4,%5,%6,%7},{%8,%9},{%0,%1,%2,%3};"                   \
                 : "+f"((c)[0]), "+f"((c)[1]), "+f"((c)[2]), "+f"((c)[3])               \
                 : "r"((a)[0]), "r"((a)[1]), "r"((a)[2]), "r"((a)[3]),                  \
                   "r"((b)[0]), "r"((b)[1]))

__device__ __forceinline__ void ld_tile_p(uint32_t sbase, const uint64_t* __restrict__ rp,
                                          uint32_t koff, int tid) {
    #pragma unroll
    for (int c = tid; c < 1024; c += 256) {
        int row = c >> 3, ch = c & 7;
        const char* gp = (const char*)(rp[row] + koff) + ch * 16;
        uint32_t off = (uint32_t)(row * 128 + ((ch ^ (row & 7)) << 4));
        CPA(sbase + off, gp);
    }
}

// ---------------------------------------------------------------------------
// Router: combine + pair id + fp16(x); also converts weights and resets counters.
// ---------------------------------------------------------------------------
__global__ __launch_bounds__(256) void router_kernel(
    const float* __restrict__ x, const float* __restrict__ rw, const float* __restrict__ rb,
    const float* __restrict__ w1, const float* __restrict__ w2)
{
    if (blockIdx.x == 0 && threadIdx.x < 16) {
        if (threadIdx.x < 8) g_cnt[threadIdx.x] = 0;
        else if (threadIdx.x == 8) g_item = 0;
        else g_done[threadIdx.x - 9] = 0;
    }
    // weight conversion spread over the grid
    {
        const int N1 = E_NUM * HD_DIM * C_DIM;
        for (int i = blockIdx.x * 256 + threadIdx.x; i < N1; i += gridDim.x * 256) {
            g_w1h[i] = __float2half_rn(w1[i]);
            g_w2h[i] = __float2half_rn(w2[i]);
        }
    }
    int warp = threadIdx.x >> 5, lane = threadIdx.x & 31;
    int t = blockIdx.x * 8 + warp;
    const float* xr = x + (size_t)t * C_DIM;
    __half* xo = g_xh + (size_t)t * C_DIM;
    float a0 = 0.f, a1 = 0.f, a2 = 0.f, a3 = 0.f;
    for (int c = lane * 4; c < C_DIM; c += 128) {
        float4 xv = *(const float4*)(xr + c);
        float4 w0 = *(const float4*)(rw + 0 * C_DIM + c);
        float4 w1v = *(const float4*)(rw + 1 * C_DIM + c);
        float4 w2v = *(const float4*)(rw + 2 * C_DIM + c);
        float4 w3 = *(const float4*)(rw + 3 * C_DIM + c);
        a0 += xv.x*w0.x + xv.y*w0.y + xv.z*w0.z + xv.w*w0.w;
        a1 += xv.x*w1v.x + xv.y*w1v.y + xv.z*w1v.z + xv.w*w1v.w;
        a2 += xv.x*w2v.x + xv.y*w2v.y + xv.z*w2v.z + xv.w*w2v.w;
        a3 += xv.x*w3.x + xv.y*w3.y + xv.z*w3.z + xv.w*w3.w;
        __half2 h0 = __floats2half2_rn(xv.x, xv.y);
        __half2 h1 = __floats2half2_rn(xv.z, xv.w);
        *(uint2*)(xo + c) = make_uint2(*(uint32_t*)&h0, *(uint32_t*)&h1);
    }
    #pragma unroll
    for (int o = 16; o > 0; o >>= 1) {
        a0 += __shfl_xor_sync(0xffffffffu, a0, o);
        a1 += __shfl_xor_sync(0xffffffffu, a1, o);
        a2 += __shfl_xor_sync(0xffffffffu, a2, o);
        a3 += __shfl_xor_sync(0xffffffffu, a3, o);
    }
    if (lane == 0) {
        float l[4] = { a0 + rb[0], a1 + rb[1], a2 + rb[2], a3 + rb[3] };
        float mx = fmaxf(fmaxf(l[0], l[1]), fmaxf(l[2], l[3]));
        float p[4]; float Z = 0.f;
        #pragma unroll
        for (int e = 0; e < 4; e++) { p[e] = expf(l[e] - mx); Z += p[e]; }
        #pragma unroll
        for (int e = 0; e < 4; e++) p[e] /= Z;
        int i0 = 0;
        #pragma unroll
        for (int e = 1; e < 4; e++) if (p[e] > p[i0]) i0 = e;
        int i1 = (i0 == 0) ? 1 : 0;
        #pragma unroll
        for (int e = 0; e < 4; e++) if (e != i0 && p[e] > p[i1]) i1 = e;
        float s = p[i0] + p[i1] + 1e-8f;
        float ov[4] = {0.f, 0.f, 0.f, 0.f};
        ov[i0] = p[i0] / s; ov[i1] = p[i1] / s;
        ((float4*)g_combine)[t] = make_float4(ov[0], ov[1], ov[2], ov[3]);
        int lo = min(i0, i1), hi = max(i0, i1);
        g_pair[t] = (lo == 0) ? hi - 1 : ((lo == 1) ? hi + 1 : 5);
    }
}

// ---------------------------------------------------------------------------
__global__ __launch_bounds__(256) void bucketize_kernel()
{
    int t = blockIdx.x * 256 + threadIdx.x;
    int pid = g_pair[t];
    unsigned mask = __match_any_sync(0xffffffffu, pid);
    int leader = __ffs(mask) - 1;
    int rank = __popc(mask & ((1u << (threadIdx.x & 31)) - 1));
    int base = 0;
    if ((threadIdx.x & 31) == leader) base = atomicAdd(&g_cnt[pid], __popc(mask));
    base = __shfl_sync(0xffffffffu, base, leader);
    g_bucket[pid * T_TOK + base + rank] = t;
}

// ---------------------------------------------------------------------------
// One GEMM tile (128x128), MODE 1 = fc1, MODE 2 = fc2.
// ---------------------------------------------------------------------------
template <int MODE>
__device__ __forceinline__ void gemm_item(
    int b, int cnt, int m0, int n0,
    const float* __restrict__ bias, float* __restrict__ outp,
    char* smc, uint32_t sb)
{
    constexpr int NKI = (MODE == 1) ? (C_DIM / KB) : (384 / KB);   // 12 / 6
    uint64_t* rpA = (uint64_t*)(smc + TBL_OFF);
    uint64_t* rpB = rpA + 128;
    int* stok = (int*)(rpB + 128);
    const int e0 = c_pairs[b][0], e1 = c_pairs[b][1];

    const int tid = threadIdx.x, lane = tid & 31, w = tid >> 5;
    const int wm = w & 1, wn = w >> 1;
    const int lq = lane >> 2, lr = lane & 3;

    if (tid < 128) {
        int p = m0 + tid;
        int t = g_bucket[b * T_TOK + (p < cnt ? p : m0)];
        stok[tid] = t;
        rpA[tid] = (MODE == 1)
            ? (uint64_t)(const char*)(g_xh + (size_t)t * C_DIM)
            : (uint64_t)(const char*)(g_hmid + (size_t)t * 384);
    } else {
        int row = tid - 128;
        if (MODE == 1) {
            int n = n0 + row;
            int e = (n < HD_DIM) ? e0 : e1;
            int h = (n < HD_DIM) ? n : n - HD_DIM;
            rpB[row] = (uint64_t)(const char*)(g_w1h + ((size_t)e * HD_DIM + h) * C_DIM);
        } else {
            rpB[row] = (uint64_t)(const char*)(g_w2h + (size_t)(n0 + row) * HD_DIM);
        }
    }
    __syncthreads();

    auto koffB = [&](int i) -> uint32_t {
        if (MODE == 1) return (uint32_t)(i * 128);
        int e = i / 3;
        int h0 = (i - e * 3) * KB;
        return (uint32_t)(((e == 0) ? e0 : e1) * C_DIM * HD_DIM + h0) * 2u;
    };

    const int ms = lane >> 3, rl = lane & 7;
    const int a_ms2 = ms >> 1;
    const int b_ms1 = ms & 1;
    uint32_t a_rowoff[4], b_rowoff[2];
    #pragma unroll
    for (int mi = 0; mi < 4; mi++)
        a_rowoff[mi] = (uint32_t)((wm * 64 + mi * 16 + (ms & 1) * 8 + rl) * 128);
    #pragma unroll
    for (int p = 0; p < 2; p++)
        b_rowoff[p] = (uint32_t)((wn * 32 + p * 16 + (ms >> 1) * 8 + rl) * 128);

    float acc[4][4][4] = {};

    #pragma unroll
    for (int p = 0; p < 2; p++) {
        ld_tile_p(sb + p * STG_B, rpA, (uint32_t)(p * 128), tid);
        ld_tile_p(sb + p * STG_B + 16384, rpB, koffB(p), tid);
        CPC();
    }

    for (int i = 0; i < NKI; i++) {
        if (i < NKI - 1) { CPW(1); } else { CPW(0); }
        __syncthreads();
        if (i + 2 < NKI) {
            const int s2 = (i + 2) % 3;
            ld_tile_p(sb + s2 * STG_B, rpA, (uint32_t)((i + 2) * 128), tid);
            ld_tile_p(sb + s2 * STG_B + 16384, rpB, koffB(i + 2), tid);
            CPC();
        }
        const uint32_t smA = sb + (i % 3) * STG_B;
        const uint32_t smB = smA + 16384;

        #pragma unroll
        for (int kk = 0; kk < 4; kk++) {
            uint32_t a[4][4], bb[4][2];
            const uint32_t koA = (uint32_t)(((2 * kk + a_ms2) ^ rl) << 4);
            const uint32_t koB = (uint32_t)(((2 * kk + b_ms1) ^ rl) << 4);
            #pragma unroll
            for (int mi = 0; mi < 4; mi++)
                LDSM4(a[mi][0], a[mi][1], a[mi][2], a[mi][3], smA + a_rowoff[mi] + koA);
            #pragma unroll
            for (int p = 0; p < 2; p++)
                LDSM4(bb[2*p][0], bb[2*p][1], bb[2*p+1][0], bb[2*p+1][1],
                      smB + b_rowoff[p] + koB);
            #pragma unroll
            for (int mi = 0; mi < 4; mi++)
                #pragma unroll
                for (int nj = 0; nj < 4; nj++)
                    MMA16(acc[mi][nj], a[mi], bb[nj]);
        }
        // single barrier per iter: top-of-next-iter sync protects stage reuse
    }

    #pragma unroll
    for (int mi = 0; mi < 4; mi++) {
        #pragma unroll
        for (int half = 0; half < 2; half++) {
            const int rloc = wm * 64 + mi * 16 + lq + half * 8;
            if (m0 + rloc >= cnt) continue;
            const int t = stok[rloc];
            if (MODE == 1) {
                __half* orow = g_hmid + (size_t)t * 384;
                #pragma unroll
                for (int nj = 0; nj < 4; nj++) {
                    const int n = n0 + wn * 32 + nj * 8 + lr * 2;
                    const int e = (n < HD_DIM) ? e0 : e1;
                    const int h = (n < HD_DIM) ? n : n - HD_DIM;
                    const float cw = g_combine[t * 4 + e];
                    float vv[2];
                    #pragma unroll
                    for (int u = 0; u < 2; u++) {
                        float d = acc[mi][nj][half * 2 + u] + __ldg(&bias[e * HD_DIM + h + u]);
                        float g = 0.5f * d * (1.0f + erff(d * 0.70710678118654752f));
                        vv[u] = g * cw;
                    }
                    __half2 hv = __floats2half2_rn(vv[0], vv[1]);
                    *(__half2*)(orow + n) = hv;
                }
            } else {
                const float4 cw = ((const float4*)g_combine)[t];
                float* orow = outp + (size_t)t * C_DIM;
                #pragma unroll
                for (int nj = 0; nj < 4; nj++) {
                    const int n = n0 + wn * 32 + nj * 8 + lr * 2;
                    float2 v;
                    #pragma unroll
                    for (int u = 0; u < 2; u++) {
                        const int c = n + u;
                        float bv = cw.x * __ldg(&bias[0 * C_DIM + c])
                                 + cw.y * __ldg(&bias[1 * C_DIM + c])
                                 + cw.z * __ldg(&bias[2 * C_DIM + c])
                                 + cw.w * __ldg(&bias[3 * C_DIM + c]);
                        ((float*)&v)[u] = acc[mi][nj][half * 2 + u] + bv;
                    }
                    *(float2*)(orow + n) = v;
                }
            }
        }
    }
}

// ---------------------------------------------------------------------------
// Persistent fused scheduler: fc1 items first (bucket-major, nt fastest),
// then fc2 items gated per-bucket on fc1 completion counters.
// ---------------------------------------------------------------------------
__global__ __launch_bounds__(256, 2)
void moe_fused(const float* __restrict__ b1, const float* __restrict__ b2,
               float* __restrict__ outp)
{
    extern __shared__ __align__(128) char smc[];
    const uint32_t sb = smem_u32(smc);
    int* sh_item = (int*)(smc + TBL_OFF + 2048 + 64);
    const int tid = threadIdx.x;

    int cnt_[6], mt_[6];
    int tot1 = 0, tot2 = 0;
    #pragma unroll
    for (int e = 0; e < 6; e++) {
        cnt_[e] = __ldg(&g_cnt[e]);
        mt_[e] = (cnt_[e] + 127) >> 7;
        tot1 += mt_[e] * 3;
        tot2 += mt_[e] * 6;
    }
    const int TOT = tot1 + tot2;

    while (true) {
        if (tid == 0) *sh_item = atomicAdd(&g_item, 1);
        __syncthreads();
        const int item = *sh_item;
        __syncthreads();
        if (item >= TOT) break;

        int b = 0, mt = 0, nt = 0, mode;
        if (item < tot1) {
            mode = 1;
            int it = item;
            #pragma unroll
            for (int e = 0; e < 6; e++) {
                int n = mt_[e] * 3;
                if (it < n) { b = e; mt = it / 3; nt = it % 3; break; }
                it -= n;
            }
        } else {
            mode = 2;
            int it = item - tot1;
            #pragma unroll
            for (int e = 0; e < 6; e++) {
                int n = mt_[e] * 6;
                if (it < n) { b = e; mt = it / 6; nt = it % 6; break; }
                it -= n;
            }
            if (tid == 0) {
                const int need = mt_[b] * 3;
                while (*(volatile int*)&g_done[b] < need) { }
            }
        }

        if (mode == 1)
            gemm_item<1>(b, cnt_[b], mt * 128, nt * 128, b1, nullptr, smc, sb);
        else
            gemm_item<2>(b, cnt_[b], mt * 128, nt * 128, b2, outp, smc, sb);

        __syncthreads();   // all epilogue writes + smem reads of this item done
        if (mode == 1 && tid == 0) {
            __threadfence();
            atomicAdd(&g_done[b], 1);
        }
    }
}

// ---------------------------------------------------------------------------
extern "C" void kernel_launch(void* const* d_in, const int* in_sizes, int n_in,
                              void* d_out, int out_size)
{
    const float* x  = (const float*)d_in[0];
    const float* rw = (const float*)d_in[1];
    const float* rb = (const float*)d_in[2];
    const float* w1 = (const float*)d_in[3];
    const float* b1 = (const float*)d_in[4];
    const float* w2 = (const float*)d_in[5];
    const float* b2 = (const float*)d_in[6];
    float* out = (float*)d_out;

    static int nsm = 0;
    if (nsm == 0) {
        cudaDeviceGetAttribute(&nsm, cudaDevAttrMultiProcessorCount, 0);
        cudaFuncSetAttribute(moe_fused, cudaFuncAttributeMaxDynamicSharedMemorySize, SMEM_TOT);
    }

    router_kernel<<<T_TOK / 8, 256>>>(x, rw, rb, w1, w2);
    bucketize_kernel<<<T_TOK / 256, 256>>>();
    moe_fused<<<2 * nsm, 256, SMEM_TOT>>>(b1, b2, out);
}

// round 11
// speedup vs baseline: 1.0767x; 1.0261x over previous
#include <cuda_runtime.h>
#include <cuda_fp16.h>
#include <math.h>
#include <stdint.h>

#define T_TOK 32768
#define C_DIM 768
#define E_NUM 4
#define HD_DIM 192
#define KB 64                           // 64 halfs per k-iter (128B rows)
#define STG_B 32768                     // bytes per stage: A 16KB + B 16KB
#define TBL_OFF (3 * STG_B)
#define SMEM_TOT (3 * STG_B + 2048 + 512 + 128)

__device__ float  g_combine[T_TOK * E_NUM];
__device__ int    g_cnt[8];
__device__ int    g_item;
__device__ int    g_done[8];
__device__ int    g_bucket[6 * T_TOK];
__device__ __half g_xh[(size_t)T_TOK * C_DIM];
__device__ __half g_hmid[(size_t)T_TOK * 384];
__device__ __half g_w1h[E_NUM * HD_DIM * C_DIM];
__device__ __half g_w2h[E_NUM * C_DIM * HD_DIM];

__constant__ int c_pairs[6][2] = {{0,1},{0,2},{0,3},{1,2},{1,3},{2,3}};

// ---------------- helpers ----------------
__device__ __forceinline__ uint32_t smem_u32(const void* p) {
    uint32_t a;
    asm("{ .reg .u64 t; cvta.to.shared.u64 t, %1; cvt.u32.u64 %0, t; }" : "=r"(a) : "l"(p));
    return a;
}
#define CPA(s, g)  asm volatile("cp.async.cg.shared.global [%0], [%1], 16;" :: "r"(s), "l"(g))
#define CPC()      asm volatile("cp.async.commit_group;" ::: "memory")
#define CPW(n)     asm volatile("cp.async.wait_group %0;" :: "n"(n) : "memory")

#define LDSM4(r0, r1, r2, r3, addr)                                                     \
    asm volatile("ldmatrix.sync.aligned.m8n8.x4.shared.b16 {%0,%1,%2,%3}, [%4];"        \
                 : "=r"(r0), "=r"(r1), "=r"(r2), "=r"(r3) : "r"(addr))

#define MMA16(c, a, b)                                                                  \
    asm volatile("mma.sync.aligned.m16n8k16.row.col.f32.f16.f16.f32 "                   \
                 "{%0,%1,%2,%3},{%4,%5,%6,%7},{%8,%9},{%0,%1,%2,%3};"                   \
                 : "+f"((c)[0]), "+f"((c)[1]), "+f"((c)[2]), "+f"((c)[3])               \
                 : "r"((a)[0]), "r"((a)[1]), "r"((a)[2]), "r"((a)[3]),                  \
                   "r"((b)[0]), "r"((b)[1]))

__device__ __forceinline__ void ld_tile_p(uint32_t sbase, const uint64_t* __restrict__ rp,
                                          uint32_t koff, int tid) {
    #pragma unroll
    for (int c = tid; c < 1024; c += 256) {
        int row = c >> 3, ch = c & 7;
        const char* gp = (const char*)(rp[row] + koff) + ch * 16;
        uint32_t off = (uint32_t)(row * 128 + ((ch ^ (row & 7)) << 4));
        CPA(sbase + off, gp);
    }
}

// ---------------------------------------------------------------------------
__global__ void zero_kernel()
{
    if (threadIdx.x < 8) g_cnt[threadIdx.x] = 0;
    else if (threadIdx.x == 8) g_item = 0;
    else if (threadIdx.x < 15) g_done[threadIdx.x - 9] = 0;
}

// ---------------------------------------------------------------------------
// Router: 2 tokens per warp -> combine + pair id + fp16(x); converts weights;
// block-aggregated bucket append (bucketize fused).
// ---------------------------------------------------------------------------
__global__ __launch_bounds__(256) void router_kernel(
    const float* __restrict__ x, const float* __restrict__ rw, const float* __restrict__ rb,
    const float* __restrict__ w1, const float* __restrict__ w2)
{
    __shared__ int s_pair[16];
    // weight conversion spread over the grid
    {
        const int N1 = E_NUM * HD_DIM * C_DIM;
        for (int i = blockIdx.x * 256 + threadIdx.x; i < N1; i += gridDim.x * 256) {
            g_w1h[i] = __float2half_rn(w1[i]);
            g_w2h[i] = __float2half_rn(w2[i]);
        }
    }
    const int warp = threadIdx.x >> 5, lane = threadIdx.x & 31;
    const int t0 = blockIdx.x * 16 + warp * 2;
    const float* xr0 = x + (size_t)t0 * C_DIM;
    const float* xr1 = xr0 + C_DIM;
    __half* xo0 = g_xh + (size_t)t0 * C_DIM;
    __half* xo1 = xo0 + C_DIM;

    float a0[4] = {0.f, 0.f, 0.f, 0.f};
    float a1[4] = {0.f, 0.f, 0.f, 0.f};
    for (int c = lane * 4; c < C_DIM; c += 128) {
        float4 x0 = *(const float4*)(xr0 + c);
        float4 x1 = *(const float4*)(xr1 + c);
        #pragma unroll
        for (int e = 0; e < 4; e++) {
            float4 wv = *(const float4*)(rw + e * C_DIM + c);
            a0[e] += x0.x*wv.x + x0.y*wv.y + x0.z*wv.z + x0.w*wv.w;
            a1[e] += x1.x*wv.x + x1.y*wv.y + x1.z*wv.z + x1.w*wv.w;
        }
        __half2 h0 = __floats2half2_rn(x0.x, x0.y);
        __half2 h1 = __floats2half2_rn(x0.z, x0.w);
        *(uint2*)(xo0 + c) = make_uint2(*(uint32_t*)&h0, *(uint32_t*)&h1);
        __half2 h2 = __floats2half2_rn(x1.x, x1.y);
        __half2 h3 = __floats2half2_rn(x1.z, x1.w);
        *(uint2*)(xo1 + c) = make_uint2(*(uint32_t*)&h2, *(uint32_t*)&h3);
    }
    #pragma unroll
    for (int o = 16; o > 0; o >>= 1) {
        #pragma unroll
        for (int e = 0; e < 4; e++) {
            a0[e] += __shfl_xor_sync(0xffffffffu, a0[e], o);
            a1[e] += __shfl_xor_sync(0xffffffffu, a1[e], o);
        }
    }
    if (lane < 2) {
        const float* av = (lane == 0) ? a0 : a1;
        const int t = t0 + lane;
        float l[4];
        #pragma unroll
        for (int e = 0; e < 4; e++) l[e] = av[e] + rb[e];
        float mx = fmaxf(fmaxf(l[0], l[1]), fmaxf(l[2], l[3]));
        float p[4]; float Z = 0.f;
        #pragma unroll
        for (int e = 0; e < 4; e++) { p[e] = expf(l[e] - mx); Z += p[e]; }
        #pragma unroll
        for (int e = 0; e < 4; e++) p[e] /= Z;
        int i0 = 0;
        #pragma unroll
        for (int e = 1; e < 4; e++) if (p[e] > p[i0]) i0 = e;
        int i1 = (i0 == 0) ? 1 : 0;
        #pragma unroll
        for (int e = 0; e < 4; e++) if (e != i0 && p[e] > p[i1]) i1 = e;
        float s = p[i0] + p[i1] + 1e-8f;
        float ov[4] = {0.f, 0.f, 0.f, 0.f};
        ov[i0] = p[i0] / s; ov[i1] = p[i1] / s;
        ((float4*)g_combine)[t] = make_float4(ov[0], ov[1], ov[2], ov[3]);
        int lo = min(i0, i1), hi = max(i0, i1);
        s_pair[warp * 2 + lane] = (lo == 0) ? hi - 1 : ((lo == 1) ? hi + 1 : 5);
    }
    __syncthreads();
    // fused bucketize: lanes 0-15 of warp 0 append this block's 16 tokens
    if (threadIdx.x < 16) {
        int pid = s_pair[threadIdx.x];
        unsigned mask = __match_any_sync(0x0000ffffu, pid) & 0xffffu;
        int leader = __ffs(mask) - 1;
        int rank = __popc(mask & ((1u << threadIdx.x) - 1));
        int base = 0;
        if (threadIdx.x == leader) base = atomicAdd(&g_cnt[pid], __popc(mask));
        base = __shfl_sync(0x0000ffffu, base, leader);
        g_bucket[pid * T_TOK + base + rank] = blockIdx.x * 16 + threadIdx.x;
    }
}

// ---------------------------------------------------------------------------
// One GEMM tile (128x128), MODE 1 = fc1, MODE 2 = fc2.
// ---------------------------------------------------------------------------
template <int MODE>
__device__ __forceinline__ void gemm_item(
    int b, int cnt, int m0, int n0,
    const float* __restrict__ bias, float* __restrict__ outp,
    char* smc, uint32_t sb)
{
    constexpr int NKI = (MODE == 1) ? (C_DIM / KB) : (384 / KB);   // 12 / 6
    uint64_t* rpA = (uint64_t*)(smc + TBL_OFF);
    uint64_t* rpB = rpA + 128;
    int* stok = (int*)(rpB + 128);
    const int e0 = c_pairs[b][0], e1 = c_pairs[b][1];

    const int tid = threadIdx.x, lane = tid & 31, w = tid >> 5;
    const int wm = w & 1, wn = w >> 1;
    const int lq = lane >> 2, lr = lane & 3;

    if (tid < 128) {
        int p = m0 + tid;
        int t = g_bucket[b * T_TOK + (p < cnt ? p : m0)];
        stok[tid] = t;
        rpA[tid] = (MODE == 1)
            ? (uint64_t)(const char*)(g_xh + (size_t)t * C_DIM)
            : (uint64_t)(const char*)(g_hmid + (size_t)t * 384);
    } else {
        int row = tid - 128;
        if (MODE == 1) {
            int n = n0 + row;
            int e = (n < HD_DIM) ? e0 : e1;
            int h = (n < HD_DIM) ? n : n - HD_DIM;
            rpB[row] = (uint64_t)(const char*)(g_w1h + ((size_t)e * HD_DIM + h) * C_DIM);
        } else {
            rpB[row] = (uint64_t)(const char*)(g_w2h + (size_t)(n0 + row) * HD_DIM);
        }
    }
    __syncthreads();

    auto koffB = [&](int i) -> uint32_t {
        if (MODE == 1) return (uint32_t)(i * 128);
        int e = i / 3;
        int h0 = (i - e * 3) * KB;
        return (uint32_t)(((e == 0) ? e0 : e1) * C_DIM * HD_DIM + h0) * 2u;
    };

    const int ms = lane >> 3, rl = lane & 7;
    const int a_ms2 = ms >> 1;
    const int b_ms1 = ms & 1;
    uint32_t a_rowoff[4], b_rowoff[2];
    #pragma unroll
    for (int mi = 0; mi < 4; mi++)
        a_rowoff[mi] = (uint32_t)((wm * 64 + mi * 16 + (ms & 1) * 8 + rl) * 128);
    #pragma unroll
    for (int p = 0; p < 2; p++)
        b_rowoff[p] = (uint32_t)((wn * 32 + p * 16 + (ms >> 1) * 8 + rl) * 128);

    float acc[4][4][4] = {};

    #pragma unroll
    for (int p = 0; p < 2; p++) {
        ld_tile_p(sb + p * STG_B, rpA, (uint32_t)(p * 128), tid);
        ld_tile_p(sb + p * STG_B + 16384, rpB, koffB(p), tid);
        CPC();
    }

    for (int i = 0; i < NKI; i++) {
        if (i < NKI - 1) { CPW(1); } else { CPW(0); }
        __syncthreads();
        if (i + 2 < NKI) {
            const int s2 = (i + 2) % 3;
            ld_tile_p(sb + s2 * STG_B, rpA, (uint32_t)((i + 2) * 128), tid);
            ld_tile_p(sb + s2 * STG_B + 16384, rpB, koffB(i + 2), tid);
            CPC();
        }
        const uint32_t smA = sb + (i % 3) * STG_B;
        const uint32_t smB = smA + 16384;

        #pragma unroll
        for (int kk = 0; kk < 4; kk++) {
            uint32_t a[4][4], bb[4][2];
            const uint32_t koA = (uint32_t)(((2 * kk + a_ms2) ^ rl) << 4);
            const uint32_t koB = (uint32_t)(((2 * kk + b_ms1) ^ rl) << 4);
            #pragma unroll
            for (int mi = 0; mi < 4; mi++)
                LDSM4(a[mi][0], a[mi][1], a[mi][2], a[mi][3], smA + a_rowoff[mi] + koA);
            #pragma unroll
            for (int p = 0; p < 2; p++)
                LDSM4(bb[2*p][0], bb[2*p][1], bb[2*p+1][0], bb[2*p+1][1],
                      smB + b_rowoff[p] + koB);
            #pragma unroll
            for (int mi = 0; mi < 4; mi++)
                #pragma unroll
                for (int nj = 0; nj < 4; nj++)
                    MMA16(acc[mi][nj], a[mi], bb[nj]);
        }
    }

    #pragma unroll
    for (int mi = 0; mi < 4; mi++) {
        #pragma unroll
        for (int half = 0; half < 2; half++) {
            const int rloc = wm * 64 + mi * 16 + lq + half * 8;
            if (m0 + rloc >= cnt) continue;
            const int t = stok[rloc];
            if (MODE == 1) {
                __half* orow = g_hmid + (size_t)t * 384;
                #pragma unroll
                for (int nj = 0; nj < 4; nj++) {
                    const int n = n0 + wn * 32 + nj * 8 + lr * 2;
                    const int e = (n < HD_DIM) ? e0 : e1;
                    const int h = (n < HD_DIM) ? n : n - HD_DIM;
                    const float cw = g_combine[t * 4 + e];
                    float vv[2];
                    #pragma unroll
                    for (int u = 0; u < 2; u++) {
                        float d = acc[mi][nj][half * 2 + u] + __ldg(&bias[e * HD_DIM + h + u]);
                        float g = 0.5f * d * (1.0f + erff(d * 0.70710678118654752f));
                        vv[u] = g * cw;
                    }
                    __half2 hv = __floats2half2_rn(vv[0], vv[1]);
                    *(__half2*)(orow + n) = hv;
                }
            } else {
                const float4 cw = ((const float4*)g_combine)[t];
                float* orow = outp + (size_t)t * C_DIM;
                #pragma unroll
                for (int nj = 0; nj < 4; nj++) {
                    const int n = n0 + wn * 32 + nj * 8 + lr * 2;
                    float2 v;
                    #pragma unroll
                    for (int u = 0; u < 2; u++) {
                        const int c = n + u;
                        float bv = cw.x * __ldg(&bias[0 * C_DIM + c])
                                 + cw.y * __ldg(&bias[1 * C_DIM + c])
                                 + cw.z * __ldg(&bias[2 * C_DIM + c])
                                 + cw.w * __ldg(&bias[3 * C_DIM + c]);
                        ((float*)&v)[u] = acc[mi][nj][half * 2 + u] + bv;
                    }
                    *(float2*)(orow + n) = v;
                }
            }
        }
    }
}

// ---------------------------------------------------------------------------
// Persistent fused scheduler: fc1 items first, then fc2 gated per bucket.
// ---------------------------------------------------------------------------
__global__ __launch_bounds__(256, 2)
void moe_fused(const float* __restrict__ b1, const float* __restrict__ b2,
               float* __restrict__ outp)
{
    extern __shared__ __align__(128) char smc[];
    const uint32_t sb = smem_u32(smc);
    int* sh_item = (int*)(smc + TBL_OFF + 2048 + 64);
    const int tid = threadIdx.x;

    int cnt_[6], mt_[6];
    int tot1 = 0, tot2 = 0;
    #pragma unroll
    for (int e = 0; e < 6; e++) {
        cnt_[e] = __ldg(&g_cnt[e]);
        mt_[e] = (cnt_[e] + 127) >> 7;
        tot1 += mt_[e] * 3;
        tot2 += mt_[e] * 6;
    }
    const int TOT = tot1 + tot2;

    while (true) {
        if (tid == 0) *sh_item = atomicAdd(&g_item, 1);
        __syncthreads();
        const int item = *sh_item;
        __syncthreads();
        if (item >= TOT) break;

        int b = 0, mt = 0, nt = 0, mode;
        if (item < tot1) {
            mode = 1;
            int it = item;
            #pragma unroll
            for (int e = 0; e < 6; e++) {
                int n = mt_[e] * 3;
                if (it < n) { b = e; mt = it / 3; nt = it % 3; break; }
                it -= n;
            }
        } else {
            mode = 2;
            int it = item - tot1;
            #pragma unroll
            for (int e = 0; e < 6; e++) {
                int n = mt_[e] * 6;
                if (it < n) { b = e; mt = it / 6; nt = it % 6; break; }
                it -= n;
            }
            if (tid == 0) {
                const int need = mt_[b] * 3;
                while (*(volatile int*)&g_done[b] < need) { }
            }
        }

        if (mode == 1)
            gemm_item<1>(b, cnt_[b], mt * 128, nt * 128, b1, nullptr, smc, sb);
        else
            gemm_item<2>(b, cnt_[b], mt * 128, nt * 128, b2, outp, smc, sb);

        __syncthreads();
        if (mode == 1 && tid == 0) {
            __threadfence();
            atomicAdd(&g_done[b], 1);
        }
    }
}

// ---------------------------------------------------------------------------
extern "C" void kernel_launch(void* const* d_in, const int* in_sizes, int n_in,
                              void* d_out, int out_size)
{
    const float* x  = (const float*)d_in[0];
    const float* rw = (const float*)d_in[1];
    const float* rb = (const float*)d_in[2];
    const float* w1 = (const float*)d_in[3];
    const float* b1 = (const float*)d_in[4];
    const float* w2 = (const float*)d_in[5];
    const float* b2 = (const float*)d_in[6];
    float* out = (float*)d_out;

    static int nsm = 0;
    if (nsm == 0) {
        cudaDeviceGetAttribute(&nsm, cudaDevAttrMultiProcessorCount, 0);
        cudaFuncSetAttribute(moe_fused, cudaFuncAttributeMaxDynamicSharedMemorySize, SMEM_TOT);
    }

    zero_kernel<<<1, 32>>>();
    router_kernel<<<T_TOK / 16, 256>>>(x, rw, rb, w1, w2);
    moe_fused<<<2 * nsm, 256, SMEM_TOT>>>(b1, b2, out);
}

// round 12
// speedup vs baseline: 1.0811x; 1.0041x over previous
#include <cuda_runtime.h>
#include <cuda_fp16.h>
#include <math.h>
#include <stdint.h>

#define T_TOK 32768
#define C_DIM 768
#define E_NUM 4
#define HD_DIM 192
#define KB 64                           // 64 halfs per k-iter (128B rows)
#define STG_B 32768                     // bytes per stage: A 16KB + B 16KB
#define TBL_OFF (3 * STG_B)
#define SMEM_TOT (3 * STG_B + 2048 + 512 + 128)

__device__ float  g_combine[T_TOK * E_NUM];
__device__ int    g_cnt[8];
__device__ int    g_item;
__device__ int    g_fin;
__device__ int    g_done[8];
__device__ int    g_bucket[6 * T_TOK];
__device__ __half g_xh[(size_t)T_TOK * C_DIM];
__device__ __half g_hmid[(size_t)T_TOK * 384];
__device__ __half g_w1h[E_NUM * HD_DIM * C_DIM];
__device__ __half g_w2h[E_NUM * C_DIM * HD_DIM];

__constant__ int c_pairs[6][2] = {{0,1},{0,2},{0,3},{1,2},{1,3},{2,3}};

// ---------------- helpers ----------------
__device__ __forceinline__ uint32_t smem_u32(const void* p) {
    uint32_t a;
    asm("{ .reg .u64 t; cvta.to.shared.u64 t, %1; cvt.u32.u64 %0, t; }" : "=r"(a) : "l"(p));
    return a;
}
#define CPA(s, g)  asm volatile("cp.async.cg.shared.global [%0], [%1], 16;" :: "r"(s), "l"(g))
#define CPC()      asm volatile("cp.async.commit_group;" ::: "memory")
#define CPW(n)     asm volatile("cp.async.wait_group %0;" :: "n"(n) : "memory")

#define LDSM4(r0, r1, r2, r3, addr)                                                     \
    asm volatile("ldmatrix.sync.aligned.m8n8.x4.shared.b16 {%0,%1,%2,%3}, [%4];"        \
                 : "=r"(r0), "=r"(r1), "=r"(r2), "=r"(r3) : "r"(addr))

#define MMA16(c, a, b)                                                                  \
    asm volatile("mma.sync.aligned.m16n8k16.row.col.f32.f16.f16.f32 "                   \
                 "{%0,%1,%2,%3},{%4,%5,%6,%7},{%8,%9},{%0,%1,%2,%3};"                   \
                 : "+f"((c)[0]), "+f"((c)[1]), "+f"((c)[2]), "+f"((c)[3])               \
                 : "r"((a)[0]), "r"((a)[1]), "r"((a)[2]), "r"((a)[3]),                  \
                   "r"((b)[0]), "r"((b)[1]))

__device__ __forceinline__ void ld_tile_p(uint32_t sbase, const uint64_t* __restrict__ rp,
                                          uint32_t koff, int tid) {
    #pragma unroll
    for (int c = tid; c < 1024; c += 256) {
        int row = c >> 3, ch = c & 7;
        const char* gp = (const char*)(rp[row] + koff) + ch * 16;
        uint32_t off = (uint32_t)(row * 128 + ((ch ^ (row & 7)) << 4));
        CPA(sbase + off, gp);
    }
}

// ---------------------------------------------------------------------------
// Router: 2 tokens per warp -> combine + pair id + fp16(x); converts weights;
// block-aggregated bucket append (bucketize fused).
// ---------------------------------------------------------------------------
__global__ __launch_bounds__(256) void router_kernel(
    const float* __restrict__ x, const float* __restrict__ rw, const float* __restrict__ rb,
    const float* __restrict__ w1, const float* __restrict__ w2)
{
    __shared__ int s_pair[16];
    {
        const int N1 = E_NUM * HD_DIM * C_DIM;
        for (int i = blockIdx.x * 256 + threadIdx.x; i < N1; i += gridDim.x * 256) {
            g_w1h[i] = __float2half_rn(w1[i]);
            g_w2h[i] = __float2half_rn(w2[i]);
        }
    }
    const int warp = threadIdx.x >> 5, lane = threadIdx.x & 31;
    const int t0 = blockIdx.x * 16 + warp * 2;
    const float* xr0 = x + (size_t)t0 * C_DIM;
    const float* xr1 = xr0 + C_DIM;
    __half* xo0 = g_xh + (size_t)t0 * C_DIM;
    __half* xo1 = xo0 + C_DIM;

    float a0[4] = {0.f, 0.f, 0.f, 0.f};
    float a1[4] = {0.f, 0.f, 0.f, 0.f};
    for (int c = lane * 4; c < C_DIM; c += 128) {
        float4 x0 = *(const float4*)(xr0 + c);
        float4 x1 = *(const float4*)(xr1 + c);
        #pragma unroll
        for (int e = 0; e < 4; e++) {
            float4 wv = *(const float4*)(rw + e * C_DIM + c);
            a0[e] += x0.x*wv.x + x0.y*wv.y + x0.z*wv.z + x0.w*wv.w;
            a1[e] += x1.x*wv.x + x1.y*wv.y + x1.z*wv.z + x1.w*wv.w;
        }
        __half2 h0 = __floats2half2_rn(x0.x, x0.y);
        __half2 h1 = __floats2half2_rn(x0.z, x0.w);
        *(uint2*)(xo0 + c) = make_uint2(*(uint32_t*)&h0, *(uint32_t*)&h1);
        __half2 h2 = __floats2half2_rn(x1.x, x1.y);
        __half2 h3 = __floats2half2_rn(x1.z, x1.w);
        *(uint2*)(xo1 + c) = make_uint2(*(uint32_t*)&h2, *(uint32_t*)&h3);
    }
    #pragma unroll
    for (int o = 16; o > 0; o >>= 1) {
        #pragma unroll
        for (int e = 0; e < 4; e++) {
            a0[e] += __shfl_xor_sync(0xffffffffu, a0[e], o);
            a1[e] += __shfl_xor_sync(0xffffffffu, a1[e], o);
        }
    }
    if (lane < 2) {
        const float* av = (lane == 0) ? a0 : a1;
        const int t = t0 + lane;
        float l[4];
        #pragma unroll
        for (int e = 0; e < 4; e++) l[e] = av[e] + rb[e];
        float mx = fmaxf(fmaxf(l[0], l[1]), fmaxf(l[2], l[3]));
        float p[4]; float Z = 0.f;
        #pragma unroll
        for (int e = 0; e < 4; e++) { p[e] = expf(l[e] - mx); Z += p[e]; }
        #pragma unroll
        for (int e = 0; e < 4; e++) p[e] /= Z;
        int i0 = 0;
        #pragma unroll
        for (int e = 1; e < 4; e++) if (p[e] > p[i0]) i0 = e;
        int i1 = (i0 == 0) ? 1 : 0;
        #pragma unroll
        for (int e = 0; e < 4; e++) if (e != i0 && p[e] > p[i1]) i1 = e;
        float s = p[i0] + p[i1] + 1e-8f;
        float ov[4] = {0.f, 0.f, 0.f, 0.f};
        ov[i0] = p[i0] / s; ov[i1] = p[i1] / s;
        ((float4*)g_combine)[t] = make_float4(ov[0], ov[1], ov[2], ov[3]);
        int lo = min(i0, i1), hi = max(i0, i1);
        s_pair[warp * 2 + lane] = (lo == 0) ? hi - 1 : ((lo == 1) ? hi + 1 : 5);
    }
    __syncthreads();
    if (threadIdx.x < 16) {
        int pid = s_pair[threadIdx.x];
        unsigned mask = __match_any_sync(0x0000ffffu, pid) & 0xffffu;
        int leader = __ffs(mask) - 1;
        int rank = __popc(mask & ((1u << threadIdx.x) - 1));
        int base = 0;
        if (threadIdx.x == leader) base = atomicAdd(&g_cnt[pid], __popc(mask));
        base = __shfl_sync(0x0000ffffu, base, leader);
        g_bucket[pid * T_TOK + base + rank] = blockIdx.x * 16 + threadIdx.x;
    }
}

// ---------------------------------------------------------------------------
// One GEMM tile (128x128), MODE 1 = fc1, MODE 2 = fc2.
// ---------------------------------------------------------------------------
template <int MODE>
__device__ __forceinline__ void gemm_item(
    int b, int cnt, int m0, int n0,
    const float* __restrict__ bias, float* __restrict__ outp,
    char* smc, uint32_t sb)
{
    constexpr int NKI = (MODE == 1) ? (C_DIM / KB) : (384 / KB);   // 12 / 6
    uint64_t* rpA = (uint64_t*)(smc + TBL_OFF);
    uint64_t* rpB = rpA + 128;
    int* stok = (int*)(rpB + 128);
    const int e0 = c_pairs[b][0], e1 = c_pairs[b][1];

    const int tid = threadIdx.x, lane = tid & 31, w = tid >> 5;
    const int wm = w & 1, wn = w >> 1;
    const int lq = lane >> 2, lr = lane & 3;
    const int ph = w & 3;                       // per-warp kk phase stagger

    if (tid < 128) {
        int p = m0 + tid;
        int t = g_bucket[b * T_TOK + (p < cnt ? p : m0)];
        stok[tid] = t;
        rpA[tid] = (MODE == 1)
            ? (uint64_t)(const char*)(g_xh + (size_t)t * C_DIM)
            : (uint64_t)(const char*)(g_hmid + (size_t)t * 384);
    } else {
        int row = tid - 128;
        if (MODE == 1) {
            int n = n0 + row;
            int e = (n < HD_DIM) ? e0 : e1;
            int h = (n < HD_DIM) ? n : n - HD_DIM;
            rpB[row] = (uint64_t)(const char*)(g_w1h + ((size_t)e * HD_DIM + h) * C_DIM);
        } else {
            rpB[row] = (uint64_t)(const char*)(g_w2h + (size_t)(n0 + row) * HD_DIM);
        }
    }
    __syncthreads();

    auto koffB = [&](int i) -> uint32_t {
        if (MODE == 1) return (uint32_t)(i * 128);
        int e = i / 3;
        int h0 = (i - e * 3) * KB;
        return (uint32_t)(((e == 0) ? e0 : e1) * C_DIM * HD_DIM + h0) * 2u;
    };

    const int ms = lane >> 3, rl = lane & 7;
    const int a_ms2 = ms >> 1;
    const int b_ms1 = ms & 1;
    uint32_t a_rowoff[4], b_rowoff[2];
    #pragma unroll
    for (int mi = 0; mi < 4; mi++)
        a_rowoff[mi] = (uint32_t)((wm * 64 + mi * 16 + (ms & 1) * 8 + rl) * 128);
    #pragma unroll
    for (int p = 0; p < 2; p++)
        b_rowoff[p] = (uint32_t)((wn * 32 + p * 16 + (ms >> 1) * 8 + rl) * 128);

    float acc[4][4][4] = {};

    #pragma unroll
    for (int p = 0; p < 2; p++) {
        ld_tile_p(sb + p * STG_B, rpA, (uint32_t)(p * 128), tid);
        ld_tile_p(sb + p * STG_B + 16384, rpB, koffB(p), tid);
        CPC();
    }

    for (int i = 0; i < NKI; i++) {
        if (i < NKI - 1) { CPW(1); } else { CPW(0); }
        __syncthreads();
        if (i + 2 < NKI) {
            const int s2 = (i + 2) % 3;
            ld_tile_p(sb + s2 * STG_B, rpA, (uint32_t)((i + 2) * 128), tid);
            ld_tile_p(sb + s2 * STG_B + 16384, rpB, koffB(i + 2), tid);
            CPC();
        }
        const uint32_t smA = sb + (i % 3) * STG_B;
        const uint32_t smB = smA + 16384;

        #pragma unroll
        for (int kks = 0; kks < 4; kks++) {
            const int kk = (kks + ph) & 3;      // staggered k-chunk order
            uint32_t a[4][4], bb[4][2];
            const uint32_t koA = (uint32_t)(((2 * kk + a_ms2) ^ rl) << 4);
            const uint32_t koB = (uint32_t)(((2 * kk + b_ms1) ^ rl) << 4);
            #pragma unroll
            for (int mi = 0; mi < 4; mi++)
                LDSM4(a[mi][0], a[mi][1], a[mi][2], a[mi][3], smA + a_rowoff[mi] + koA);
            #pragma unroll
            for (int p = 0; p < 2; p++)
                LDSM4(bb[2*p][0], bb[2*p][1], bb[2*p+1][0], bb[2*p+1][1],
                      smB + b_rowoff[p] + koB);
            #pragma unroll
            for (int mi = 0; mi < 4; mi++)
                #pragma unroll
                for (int nj = 0; nj < 4; nj++)
                    MMA16(acc[mi][nj], a[mi], bb[nj]);
        }
    }

    #pragma unroll
    for (int mi = 0; mi < 4; mi++) {
        #pragma unroll
        for (int half = 0; half < 2; half++) {
            const int rloc = wm * 64 + mi * 16 + lq + half * 8;
            if (m0 + rloc >= cnt) continue;
            const int t = stok[rloc];
            if (MODE == 1) {
                __half* orow = g_hmid + (size_t)t * 384;
                #pragma unroll
                for (int nj = 0; nj < 4; nj++) {
                    const int n = n0 + wn * 32 + nj * 8 + lr * 2;
                    const int e = (n < HD_DIM) ? e0 : e1;
                    const int h = (n < HD_DIM) ? n : n - HD_DIM;
                    const float cw = g_combine[t * 4 + e];
                    float vv[2];
                    #pragma unroll
                    for (int u = 0; u < 2; u++) {
                        float d = acc[mi][nj][half * 2 + u] + __ldg(&bias[e * HD_DIM + h + u]);
                        float g = 0.5f * d * (1.0f + erff(d * 0.70710678118654752f));
                        vv[u] = g * cw;
                    }
                    __half2 hv = __floats2half2_rn(vv[0], vv[1]);
                    *(__half2*)(orow + n) = hv;
                }
            } else {
                const float4 cw = ((const float4*)g_combine)[t];
                float* orow = outp + (size_t)t * C_DIM;
                #pragma unroll
                for (int nj = 0; nj < 4; nj++) {
                    const int n = n0 + wn * 32 + nj * 8 + lr * 2;
                    float2 v;
                    #pragma unroll
                    for (int u = 0; u < 2; u++) {
                        const int c = n + u;
                        float bv = cw.x * __ldg(&bias[0 * C_DIM + c])
                                 + cw.y * __ldg(&bias[1 * C_DIM + c])
                                 + cw.z * __ldg(&bias[2 * C_DIM + c])
                                 + cw.w * __ldg(&bias[3 * C_DIM + c]);
                        ((float*)&v)[u] = acc[mi][nj][half * 2 + u] + bv;
                    }
                    *(float2*)(orow + n) = v;
                }
            }
        }
    }
}

// ---------------------------------------------------------------------------
// Persistent fused scheduler: fc1 items first, then fc2 gated per bucket.
// Last CTA resets global counters for the next graph replay.
// ---------------------------------------------------------------------------
__global__ __launch_bounds__(256, 2)
void moe_fused(const float* __restrict__ b1, const float* __restrict__ b2,
               float* __restrict__ outp)
{
    extern __shared__ __align__(128) char smc[];
    const uint32_t sb = smem_u32(smc);
    int* sh_item = (int*)(smc + TBL_OFF + 2048 + 64);
    const int tid = threadIdx.x;

    int cnt_[6], mt_[6];
    int tot1 = 0, tot2 = 0;
    #pragma unroll
    for (int e = 0; e < 6; e++) {
        cnt_[e] = __ldg(&g_cnt[e]);
        mt_[e] = (cnt_[e] + 127) >> 7;
        tot1 += mt_[e] * 3;
        tot2 += mt_[e] * 6;
    }
    const int TOT = tot1 + tot2;

    while (true) {
        if (tid == 0) *sh_item = atomicAdd(&g_item, 1);
        __syncthreads();
        const int item = *sh_item;
        __syncthreads();
        if (item >= TOT) break;

        int b = 0, mt = 0, nt = 0, mode;
        if (item < tot1) {
            mode = 1;
            int it = item;
            #pragma unroll
            for (int e = 0; e < 6; e++) {
                int n = mt_[e] * 3;
                if (it < n) { b = e; mt = it / 3; nt = it % 3; break; }
                it -= n;
            }
        } else {
            mode = 2;
            int it = item - tot1;
            #pragma unroll
            for (int e = 0; e < 6; e++) {
                int n = mt_[e] * 6;
                if (it < n) { b = e; mt = it / 6; nt = it % 6; break; }
                it -= n;
            }
            if (tid == 0) {
                const int need = mt_[b] * 3;
                while (*(volatile int*)&g_done[b] < need) { }
            }
        }

        if (mode == 1)
            gemm_item<1>(b, cnt_[b], mt * 128, nt * 128, b1, nullptr, smc, sb);
        else
            gemm_item<2>(b, cnt_[b], mt * 128, nt * 128, b2, outp, smc, sb);

        __syncthreads();
        if (mode == 1 && tid == 0) {
            __threadfence();
            atomicAdd(&g_done[b], 1);
        }
    }

    // self-reset for next graph replay: last CTA to finish clears all state
    if (tid == 0) {
        int f = atomicAdd(&g_fin, 1);
        if (f == (int)gridDim.x - 1) {
            #pragma unroll
            for (int e = 0; e < 8; e++) { g_cnt[e] = 0; g_done[e] = 0; }
            g_item = 0;
            g_fin = 0;
            __threadfence();
        }
    }
}

// ---------------------------------------------------------------------------
extern "C" void kernel_launch(void* const* d_in, const int* in_sizes, int n_in,
                              void* d_out, int out_size)
{
    const float* x  = (const float*)d_in[0];
    const float* rw = (const float*)d_in[1];
    const float* rb = (const float*)d_in[2];
    const float* w1 = (const float*)d_in[3];
    const float* b1 = (const float*)d_in[4];
    const float* w2 = (const float*)d_in[5];
    const float* b2 = (const float*)d_in[6];
    float* out = (float*)d_out;

    static int nsm = 0;
    if (nsm == 0) {
        cudaDeviceGetAttribute(&nsm, cudaDevAttrMultiProcessorCount, 0);
        cudaFuncSetAttribute(moe_fused, cudaFuncAttributeMaxDynamicSharedMemorySize, SMEM_TOT);
    }

    router_kernel<<<T_TOK / 16, 256>>>(x, rw, rb, w1, w2);
    moe_fused<<<2 * nsm, 256, SMEM_TOT>>>(b1, b2, out);
}